// round 4
// baseline (speedup 1.0000x reference)
#include <cuda_runtime.h>
#include <cstdint>

// ---------------------------------------------------------------------------
// MHA on mma.sync m16n8k8 tf32.  R4: attention instruction diet —
// fragment-linear K/V smem (LDS.64 B operands), double-buffered staging,
// exp2-folded softmax, float2 P staging.
// ---------------------------------------------------------------------------

#define SEQ     2048
#define BATCH   2
#define NH      16
#define HD      64
#define HID     1024
#define MROWS   (BATCH * SEQ)   // 4096

__device__ float g_Q[MROWS * HID];
__device__ float g_K[MROWS * HID];
__device__ float g_V[MROWS * HID];
__device__ float g_O[MROWS * HID];

// ------------------------------ helpers ------------------------------------
__device__ __forceinline__ float tf32r(float f) {
    uint32_t r;
    asm("cvt.rna.tf32.f32 %0, %1;" : "=r"(r) : "f"(f));
    return __uint_as_float(r);
}

__device__ __forceinline__ void mma_tf32(float* d, const uint32_t* a,
                                         uint32_t b0, uint32_t b1) {
    asm volatile(
        "mma.sync.aligned.m16n8k8.row.col.f32.tf32.tf32.f32 "
        "{%0,%1,%2,%3}, {%4,%5,%6,%7}, {%8,%9}, {%0,%1,%2,%3};"
        : "+f"(d[0]), "+f"(d[1]), "+f"(d[2]), "+f"(d[3])
        : "r"(a[0]), "r"(a[1]), "r"(a[2]), "r"(a[3]), "r"(b0), "r"(b1));
}

// ============================ tf32 GEMM (unchanged, passing) ================
#define PADA 36
#define PADB 136
#define GEMM_SMEM ((2 * (128 * PADA + 32 * PADB)) * (int)sizeof(float))

__global__ __launch_bounds__(256) void gemm_tc(
    const float* __restrict__ A, int lda,
    const float* __restrict__ B, int ldb,
    const float* __restrict__ bias,
    float* __restrict__ C, int ldc, int K)
{
    extern __shared__ float smg[];
    float* As = smg;
    float* Bs = smg + 2 * 128 * PADA;

    const int tid  = threadIdx.x;
    const int wid  = tid >> 5, lane = tid & 31;
    const int g    = lane >> 2, t = lane & 3;
    const int wr   = wid & 1,  wc = wid >> 1;
    const int row0 = blockIdx.y * 128;
    const int col0 = blockIdx.x * 128;

    const int ar = tid >> 3, ac = (tid & 7) * 4;
    const int br = tid >> 3, bc = (tid & 7) * 4;

    const float* Ag = A + (size_t)row0 * lda;
    const float* Bg = B + col0;

    float4 ra[4], rb[4];
    const int NT = K >> 5;

    #pragma unroll
    for (int i = 0; i < 4; i++)
        ra[i] = *(const float4*)(Ag + (size_t)(ar + 32 * i) * lda + ac);
    #pragma unroll
    for (int j = 0; j < 4; j++)
        rb[j] = *(const float4*)(Bg + (size_t)br * ldb + bc + 32 * j);
    {
        #pragma unroll
        for (int i = 0; i < 4; i++) {
            float* d = As + (ar + 32 * i) * PADA + ac;
            d[0] = tf32r(ra[i].x); d[1] = tf32r(ra[i].y);
            d[2] = tf32r(ra[i].z); d[3] = tf32r(ra[i].w);
        }
        #pragma unroll
        for (int j = 0; j < 4; j++) {
            float* d = Bs + br * PADB + bc + 32 * j;
            d[0] = tf32r(rb[j].x); d[1] = tf32r(rb[j].y);
            d[2] = tf32r(rb[j].z); d[3] = tf32r(rb[j].w);
        }
    }
    __syncthreads();

    float acc[4][4][4] = {};

    for (int kt = 0; kt < NT; kt++) {
        if (kt + 1 < NT) {
            const int k0 = (kt + 1) * 32;
            #pragma unroll
            for (int i = 0; i < 4; i++)
                ra[i] = *(const float4*)(Ag + (size_t)(ar + 32 * i) * lda + k0 + ac);
            #pragma unroll
            for (int j = 0; j < 4; j++)
                rb[j] = *(const float4*)(Bg + (size_t)(k0 + br) * ldb + bc + 32 * j);
        }

        const float* Ac = As + (kt & 1) * 128 * PADA;
        const float* Bc = Bs + (kt & 1) * 32 * PADB;

        #pragma unroll
        for (int kk = 0; kk < 4; kk++) {
            uint32_t af[4][4];
            #pragma unroll
            for (int mt = 0; mt < 4; mt++) {
                const float* ap = Ac + (wr * 64 + mt * 16) * PADA + kk * 8;
                af[mt][0] = __float_as_uint(ap[ g      * PADA + t    ]);
                af[mt][1] = __float_as_uint(ap[(g + 8) * PADA + t    ]);
                af[mt][2] = __float_as_uint(ap[ g      * PADA + t + 4]);
                af[mt][3] = __float_as_uint(ap[(g + 8) * PADA + t + 4]);
            }
            #pragma unroll
            for (int nt = 0; nt < 4; nt++) {
                const float* bp = Bc + kk * 8 * PADB + wc * 32 + nt * 8 + g;
                uint32_t b0 = __float_as_uint(bp[ t      * PADB]);
                uint32_t b1 = __float_as_uint(bp[(t + 4) * PADB]);
                #pragma unroll
                for (int mt = 0; mt < 4; mt++)
                    mma_tf32(acc[mt][nt], af[mt], b0, b1);
            }
        }

        if (kt + 1 < NT) {
            __syncthreads();
            float* Ad = As + ((kt + 1) & 1) * 128 * PADA;
            float* Bd = Bs + ((kt + 1) & 1) * 32 * PADB;
            #pragma unroll
            for (int i = 0; i < 4; i++) {
                float* d = Ad + (ar + 32 * i) * PADA + ac;
                d[0] = tf32r(ra[i].x); d[1] = tf32r(ra[i].y);
                d[2] = tf32r(ra[i].z); d[3] = tf32r(ra[i].w);
            }
            #pragma unroll
            for (int j = 0; j < 4; j++) {
                float* d = Bd + br * PADB + bc + 32 * j;
                d[0] = tf32r(rb[j].x); d[1] = tf32r(rb[j].y);
                d[2] = tf32r(rb[j].z); d[3] = tf32r(rb[j].w);
            }
            __syncthreads();
        }
    }

    #pragma unroll
    for (int mt = 0; mt < 4; mt++) {
        const int row = row0 + wr * 64 + mt * 16 + g;
        #pragma unroll
        for (int nt = 0; nt < 4; nt++) {
            const int col = col0 + wc * 32 + nt * 8 + 2 * t;
            float2 bb = *(const float2*)&bias[col];
            float2 v0 = {acc[mt][nt][0] + bb.x, acc[mt][nt][1] + bb.y};
            float2 v1 = {acc[mt][nt][2] + bb.x, acc[mt][nt][3] + bb.y};
            *(float2*)&C[(size_t)row * ldc + col]       = v0;
            *(float2*)&C[(size_t)(row + 8) * ldc + col] = v1;
        }
    }
}

// ============================ attention ====================================
// 128 q rows/CTA, 8 warps x 16 rows.  K/V staged in mma-fragment-linear
// float2 layout (B operand = one LDS.64), double-buffered; exp2 softmax.
#define ATP 68
#define KVF 4096                        // floats per fragment tile (64x64)
#define ATTN_SMEM ((4 * KVF + 128 * ATP) * (int)sizeof(float))

__global__ __launch_bounds__(256) void attn_tc(
    const float* __restrict__ Q,
    const float* __restrict__ Kin,
    const float* __restrict__ V,
    float* __restrict__ O)
{
    extern __shared__ float sma[];
    float* KF = sma;                    // [2][KVF]
    float* VF = sma + 2 * KVF;          // [2][KVF]
    float* Ps = sma + 4 * KVF;          // Q stage, then per-warp P slabs

    const int tid  = threadIdx.x;
    const int wid  = tid >> 5, lane = tid & 31;
    const int g    = lane >> 2, t = lane & 3;
    const int b    = blockIdx.z;
    const int h    = blockIdx.y;
    const int q0   = blockIdx.x * 128;
    const float C2 = 0.125f * 1.44269504088896340736f;  // scale*log2(e)

    const float* Qg = Q   + ((size_t)b * SEQ + q0) * HID + h * HD;
    const float* Kg = Kin + (size_t)b * SEQ * HID + h * HD;
    const float* Vg = V   + (size_t)b * SEQ * HID + h * HD;

    // ---- stage Q (tf32) -> fragments ----
    for (int idx = tid; idx < 128 * 16; idx += 256) {
        const int r = idx >> 4, d4 = (idx & 15) * 4;
        float4 v = *(const float4*)(Qg + (size_t)r * HID + d4);
        float* d = Ps + r * ATP + d4;
        d[0] = tf32r(v.x); d[1] = tf32r(v.y); d[2] = tf32r(v.z); d[3] = tf32r(v.w);
    }
    __syncthreads();

    uint32_t qf[8][4];
    #pragma unroll
    for (int ks = 0; ks < 8; ks++) {
        const float* qp = Ps + wid * 16 * ATP + ks * 8;
        qf[ks][0] = __float_as_uint(qp[ g      * ATP + t    ]);
        qf[ks][1] = __float_as_uint(qp[(g + 8) * ATP + t    ]);
        qf[ks][2] = __float_as_uint(qp[ g      * ATP + t + 4]);
        qf[ks][3] = __float_as_uint(qp[(g + 8) * ATP + t + 4]);
    }
    __syncthreads();

    float oacc[8][4] = {};
    float m0 = -1e30f, m1 = -1e30f, l0 = 0.0f, l1 = 0.0f;

    // staging maps
    const int jk = tid >> 2, dk = (tid & 3) * 16;    // K rows
    const int jv = tid & 63, dv = (tid >> 6) * 16;   // V rows

    float4 kreg[4], vreg[4];
    #pragma unroll
    for (int i = 0; i < 4; i++) {
        kreg[i] = *(const float4*)(Kg + (size_t)jk * HID + dk + 4 * i);
        vreg[i] = *(const float4*)(Vg + (size_t)jv * HID + dv + 4 * i);
    }

    // stage tile 0 into buffer 0
    {
        float* KD = KF; float* VD = VF;
        #pragma unroll
        for (int i = 0; i < 4; i++) {
            const int d0 = dk + 4 * i;
            const int base = (((jk >> 3) * 8 + (d0 >> 3)) << 6)
                           + ((jk & 7) * 4) * 2 + ((d0 >> 2) & 1);
            KD[base + 0] = tf32r(kreg[i].x);
            KD[base + 2] = tf32r(kreg[i].y);
            KD[base + 4] = tf32r(kreg[i].z);
            KD[base + 6] = tf32r(kreg[i].w);
            const int e0 = dv + 4 * i;
            const int vb = (((e0 >> 3) * 8 + (jv >> 3)) << 6)
                         + ((e0 & 7) * 4 + (jv & 3)) * 2 + ((jv >> 2) & 1);
            VD[vb + 0]  = tf32r(vreg[i].x);
            VD[vb + 8]  = tf32r(vreg[i].y);
            VD[vb + 16] = tf32r(vreg[i].z);
            VD[vb + 24] = tf32r(vreg[i].w);
        }
    }
    __syncthreads();

    float* Pw = Ps + wid * 16 * ATP;

    for (int kv0 = 0; kv0 < SEQ; kv0 += 64) {
        const int cur = (kv0 >> 6) & 1;
        const bool more = (kv0 + 64 < SEQ);

        if (more) {
            #pragma unroll
            for (int i = 0; i < 4; i++) {
                kreg[i] = *(const float4*)(Kg + (size_t)(kv0 + 64 + jk) * HID + dk + 4 * i);
                vreg[i] = *(const float4*)(Vg + (size_t)(kv0 + 64 + jv) * HID + dv + 4 * i);
            }
        }

        const float* KC = KF + cur * KVF;
        const float* VC = VF + cur * KVF;

        // ---- S = Q K^T ----
        float s[8][4] = {};
        #pragma unroll
        for (int ks = 0; ks < 8; ks++) {
            #pragma unroll
            for (int nt = 0; nt < 8; nt++) {
                float2 bv = *(const float2*)&KC[((nt * 8 + ks) << 6) + lane * 2];
                mma_tf32(s[nt], qf[ks], __float_as_uint(bv.x), __float_as_uint(bv.y));
            }
        }

        // ---- online softmax (raw-score max, exp2-folded) ----
        float rm0 = -1e30f, rm1 = -1e30f;
        #pragma unroll
        for (int nt = 0; nt < 8; nt++) {
            rm0 = fmaxf(rm0, fmaxf(s[nt][0], s[nt][1]));
            rm1 = fmaxf(rm1, fmaxf(s[nt][2], s[nt][3]));
        }
        rm0 = fmaxf(rm0, __shfl_xor_sync(0xffffffffu, rm0, 1));
        rm0 = fmaxf(rm0, __shfl_xor_sync(0xffffffffu, rm0, 2));
        rm1 = fmaxf(rm1, __shfl_xor_sync(0xffffffffu, rm1, 1));
        rm1 = fmaxf(rm1, __shfl_xor_sync(0xffffffffu, rm1, 2));

        const float nm0 = fmaxf(m0, rm0), nm1 = fmaxf(m1, rm1);
        const float a0 = exp2f((m0 - nm0) * C2), a1 = exp2f((m1 - nm1) * C2);
        const float mc0 = nm0 * C2, mc1 = nm1 * C2;
        float sum0 = 0.0f, sum1 = 0.0f;
        #pragma unroll
        for (int nt = 0; nt < 8; nt++) {
            s[nt][0] = exp2f(fmaf(s[nt][0], C2, -mc0)); sum0 += s[nt][0];
            s[nt][1] = exp2f(fmaf(s[nt][1], C2, -mc0)); sum0 += s[nt][1];
            s[nt][2] = exp2f(fmaf(s[nt][2], C2, -mc1)); sum1 += s[nt][2];
            s[nt][3] = exp2f(fmaf(s[nt][3], C2, -mc1)); sum1 += s[nt][3];
        }
        sum0 += __shfl_xor_sync(0xffffffffu, sum0, 1);
        sum0 += __shfl_xor_sync(0xffffffffu, sum0, 2);
        sum1 += __shfl_xor_sync(0xffffffffu, sum1, 1);
        sum1 += __shfl_xor_sync(0xffffffffu, sum1, 2);

        l0 = l0 * a0 + sum0; l1 = l1 * a1 + sum1;
        m0 = nm0; m1 = nm1;
        #pragma unroll
        for (int nt = 0; nt < 8; nt++) {
            oacc[nt][0] *= a0; oacc[nt][1] *= a0;
            oacc[nt][2] *= a1; oacc[nt][3] *= a1;
        }

        // ---- stage P (warp-private, float2) ----
        #pragma unroll
        for (int nt = 0; nt < 8; nt++) {
            float2 p0 = {tf32r(s[nt][0]), tf32r(s[nt][1])};
            float2 p1 = {tf32r(s[nt][2]), tf32r(s[nt][3])};
            *(float2*)&Pw[ g      * ATP + nt * 8 + 2 * t] = p0;
            *(float2*)&Pw[(g + 8) * ATP + nt * 8 + 2 * t] = p1;
        }
        __syncwarp();

        // ---- O += P V ----
        #pragma unroll
        for (int ks = 0; ks < 8; ks++) {
            uint32_t af[4];
            af[0] = __float_as_uint(Pw[ g      * ATP + ks * 8 + t    ]);
            af[1] = __float_as_uint(Pw[(g + 8) * ATP + ks * 8 + t    ]);
            af[2] = __float_as_uint(Pw[ g      * ATP + ks * 8 + t + 4]);
            af[3] = __float_as_uint(Pw[(g + 8) * ATP + ks * 8 + t + 4]);
            #pragma unroll
            for (int nt = 0; nt < 8; nt++) {
                float2 bv = *(const float2*)&VC[((nt * 8 + ks) << 6) + lane * 2];
                mma_tf32(oacc[nt], af, __float_as_uint(bv.x), __float_as_uint(bv.y));
            }
        }
        __syncwarp();

        // ---- stage next tile ----
        if (more) {
            float* KD = KF + (cur ^ 1) * KVF;
            float* VD = VF + (cur ^ 1) * KVF;
            #pragma unroll
            for (int i = 0; i < 4; i++) {
                const int d0 = dk + 4 * i;
                const int base = (((jk >> 3) * 8 + (d0 >> 3)) << 6)
                               + ((jk & 7) * 4) * 2 + ((d0 >> 2) & 1);
                KD[base + 0] = tf32r(kreg[i].x);
                KD[base + 2] = tf32r(kreg[i].y);
                KD[base + 4] = tf32r(kreg[i].z);
                KD[base + 6] = tf32r(kreg[i].w);
                const int e0 = dv + 4 * i;
                const int vb = (((e0 >> 3) * 8 + (jv >> 3)) << 6)
                             + ((e0 & 7) * 4 + (jv & 3)) * 2 + ((jv >> 2) & 1);
                VD[vb + 0]  = tf32r(vreg[i].x);
                VD[vb + 8]  = tf32r(vreg[i].y);
                VD[vb + 16] = tf32r(vreg[i].z);
                VD[vb + 24] = tf32r(vreg[i].w);
            }
            __syncthreads();
        }
    }

    // ---- epilogue ----
    const float inv0 = 1.0f / l0, inv1 = 1.0f / l1;
    float* Og = O + ((size_t)b * SEQ + q0 + wid * 16) * HID + h * HD;
    #pragma unroll
    for (int nt = 0; nt < 8; nt++) {
        const int col = nt * 8 + 2 * t;
        float2 v0 = {oacc[nt][0] * inv0, oacc[nt][1] * inv0};
        float2 v1 = {oacc[nt][2] * inv1, oacc[nt][3] * inv1};
        *(float2*)&Og[(size_t) g      * HID + col] = v0;
        *(float2*)&Og[(size_t)(g + 8) * HID + col] = v1;
    }
}

// ===========================================================================
extern "C" void kernel_launch(void* const* d_in, const int* in_sizes, int n_in,
                              void* d_out, int out_size)
{
    const float* q   = (const float*)d_in[0];
    const float* Wq  = (const float*)d_in[1];
    const float* bq  = (const float*)d_in[2];
    const float* Wkv = (const float*)d_in[3];
    const float* bkv = (const float*)d_in[4];
    const float* Wo  = (const float*)d_in[5];
    const float* bo  = (const float*)d_in[6];
    float* out = (float*)d_out;

    void *pQ, *pK, *pV, *pO;
    cudaGetSymbolAddress(&pQ, g_Q);
    cudaGetSymbolAddress(&pK, g_K);
    cudaGetSymbolAddress(&pV, g_V);
    cudaGetSymbolAddress(&pO, g_O);
    float* gQ = (float*)pQ;
    float* gK = (float*)pK;
    float* gV = (float*)pV;
    float* gO = (float*)pO;

    cudaFuncSetAttribute(gemm_tc, cudaFuncAttributeMaxDynamicSharedMemorySize,
                         GEMM_SMEM);
    cudaFuncSetAttribute(attn_tc, cudaFuncAttributeMaxDynamicSharedMemorySize,
                         ATTN_SMEM);

    dim3 blk(256);
    dim3 ggrid(HID / 128, MROWS / 128);

    gemm_tc<<<ggrid, blk, GEMM_SMEM>>>(q, HID, Wq, HID, bq, gQ, HID, HID);
    gemm_tc<<<ggrid, blk, GEMM_SMEM>>>(q, HID, Wkv, 2 * HID, bkv, gK, HID, HID);
    gemm_tc<<<ggrid, blk, GEMM_SMEM>>>(q, HID, Wkv + HID, 2 * HID, bkv + HID,
                                       gV, HID, HID);

    dim3 agrid(SEQ / 128, NH, BATCH);
    attn_tc<<<agrid, blk, ATTN_SMEM>>>(gQ, gK, gV, gO);

    gemm_tc<<<ggrid, blk, GEMM_SMEM>>>(gO, HID, Wo, HID, bo, out, HID, HID);
}

// round 5
// speedup vs baseline: 1.0052x; 1.0052x over previous
#include <cuda_runtime.h>
#include <cstdint>

// ---------------------------------------------------------------------------
// MHA on mma.sync m16n8k8 tf32.  R5: attention occupancy — 128-thread CTAs
// (64 q rows, 4 warps), 3 CTAs/SM via __launch_bounds__(128,3); R3 dataflow
// + exp2-folded softmax. GEMMs unchanged.
// ---------------------------------------------------------------------------

#define SEQ     2048
#define BATCH   2
#define NH      16
#define HD      64
#define HID     1024
#define MROWS   (BATCH * SEQ)   // 4096

__device__ float g_Q[MROWS * HID];
__device__ float g_K[MROWS * HID];
__device__ float g_V[MROWS * HID];
__device__ float g_O[MROWS * HID];

// ------------------------------ helpers ------------------------------------
__device__ __forceinline__ float tf32r(float f) {
    uint32_t r;
    asm("cvt.rna.tf32.f32 %0, %1;" : "=r"(r) : "f"(f));
    return __uint_as_float(r);
}

__device__ __forceinline__ void mma_tf32(float* d, const uint32_t* a,
                                         uint32_t b0, uint32_t b1) {
    asm volatile(
        "mma.sync.aligned.m16n8k8.row.col.f32.tf32.tf32.f32 "
        "{%0,%1,%2,%3}, {%4,%5,%6,%7}, {%8,%9}, {%0,%1,%2,%3};"
        : "+f"(d[0]), "+f"(d[1]), "+f"(d[2]), "+f"(d[3])
        : "r"(a[0]), "r"(a[1]), "r"(a[2]), "r"(a[3]), "r"(b0), "r"(b1));
}

// ============================ tf32 GEMM (unchanged, passing) ================
#define PADA 36
#define PADB 136
#define GEMM_SMEM ((2 * (128 * PADA + 32 * PADB)) * (int)sizeof(float))

__global__ __launch_bounds__(256) void gemm_tc(
    const float* __restrict__ A, int lda,
    const float* __restrict__ B, int ldb,
    const float* __restrict__ bias,
    float* __restrict__ C, int ldc, int K)
{
    extern __shared__ float smg[];
    float* As = smg;
    float* Bs = smg + 2 * 128 * PADA;

    const int tid  = threadIdx.x;
    const int wid  = tid >> 5, lane = tid & 31;
    const int g    = lane >> 2, t = lane & 3;
    const int wr   = wid & 1,  wc = wid >> 1;
    const int row0 = blockIdx.y * 128;
    const int col0 = blockIdx.x * 128;

    const int ar = tid >> 3, ac = (tid & 7) * 4;
    const int br = tid >> 3, bc = (tid & 7) * 4;

    const float* Ag = A + (size_t)row0 * lda;
    const float* Bg = B + col0;

    float4 ra[4], rb[4];
    const int NT = K >> 5;

    #pragma unroll
    for (int i = 0; i < 4; i++)
        ra[i] = *(const float4*)(Ag + (size_t)(ar + 32 * i) * lda + ac);
    #pragma unroll
    for (int j = 0; j < 4; j++)
        rb[j] = *(const float4*)(Bg + (size_t)br * ldb + bc + 32 * j);
    {
        #pragma unroll
        for (int i = 0; i < 4; i++) {
            float* d = As + (ar + 32 * i) * PADA + ac;
            d[0] = tf32r(ra[i].x); d[1] = tf32r(ra[i].y);
            d[2] = tf32r(ra[i].z); d[3] = tf32r(ra[i].w);
        }
        #pragma unroll
        for (int j = 0; j < 4; j++) {
            float* d = Bs + br * PADB + bc + 32 * j;
            d[0] = tf32r(rb[j].x); d[1] = tf32r(rb[j].y);
            d[2] = tf32r(rb[j].z); d[3] = tf32r(rb[j].w);
        }
    }
    __syncthreads();

    float acc[4][4][4] = {};

    for (int kt = 0; kt < NT; kt++) {
        if (kt + 1 < NT) {
            const int k0 = (kt + 1) * 32;
            #pragma unroll
            for (int i = 0; i < 4; i++)
                ra[i] = *(const float4*)(Ag + (size_t)(ar + 32 * i) * lda + k0 + ac);
            #pragma unroll
            for (int j = 0; j < 4; j++)
                rb[j] = *(const float4*)(Bg + (size_t)(k0 + br) * ldb + bc + 32 * j);
        }

        const float* Ac = As + (kt & 1) * 128 * PADA;
        const float* Bc = Bs + (kt & 1) * 32 * PADB;

        #pragma unroll
        for (int kk = 0; kk < 4; kk++) {
            uint32_t af[4][4];
            #pragma unroll
            for (int mt = 0; mt < 4; mt++) {
                const float* ap = Ac + (wr * 64 + mt * 16) * PADA + kk * 8;
                af[mt][0] = __float_as_uint(ap[ g      * PADA + t    ]);
                af[mt][1] = __float_as_uint(ap[(g + 8) * PADA + t    ]);
                af[mt][2] = __float_as_uint(ap[ g      * PADA + t + 4]);
                af[mt][3] = __float_as_uint(ap[(g + 8) * PADA + t + 4]);
            }
            #pragma unroll
            for (int nt = 0; nt < 4; nt++) {
                const float* bp = Bc + kk * 8 * PADB + wc * 32 + nt * 8 + g;
                uint32_t b0 = __float_as_uint(bp[ t      * PADB]);
                uint32_t b1 = __float_as_uint(bp[(t + 4) * PADB]);
                #pragma unroll
                for (int mt = 0; mt < 4; mt++)
                    mma_tf32(acc[mt][nt], af[mt], b0, b1);
            }
        }

        if (kt + 1 < NT) {
            __syncthreads();
            float* Ad = As + ((kt + 1) & 1) * 128 * PADA;
            float* Bd = Bs + ((kt + 1) & 1) * 32 * PADB;
            #pragma unroll
            for (int i = 0; i < 4; i++) {
                float* d = Ad + (ar + 32 * i) * PADA + ac;
                d[0] = tf32r(ra[i].x); d[1] = tf32r(ra[i].y);
                d[2] = tf32r(ra[i].z); d[3] = tf32r(ra[i].w);
            }
            #pragma unroll
            for (int j = 0; j < 4; j++) {
                float* d = Bd + br * PADB + bc + 32 * j;
                d[0] = tf32r(rb[j].x); d[1] = tf32r(rb[j].y);
                d[2] = tf32r(rb[j].z); d[3] = tf32r(rb[j].w);
            }
            __syncthreads();
        }
    }

    #pragma unroll
    for (int mt = 0; mt < 4; mt++) {
        const int row = row0 + wr * 64 + mt * 16 + g;
        #pragma unroll
        for (int nt = 0; nt < 4; nt++) {
            const int col = col0 + wc * 32 + nt * 8 + 2 * t;
            float2 bb = *(const float2*)&bias[col];
            float2 v0 = {acc[mt][nt][0] + bb.x, acc[mt][nt][1] + bb.y};
            float2 v1 = {acc[mt][nt][2] + bb.x, acc[mt][nt][3] + bb.y};
            *(float2*)&C[(size_t)row * ldc + col]       = v0;
            *(float2*)&C[(size_t)(row + 8) * ldc + col] = v1;
        }
    }
}

// ============================ attention ====================================
// 64 q rows/CTA, 4 warps x 16 rows, 3 CTAs/SM target.
#define ATP 68
#define ATTN_SMEM ((3 * 64 * ATP) * (int)sizeof(float))

__global__ __launch_bounds__(128, 3) void attn_tc(
    const float* __restrict__ Q,
    const float* __restrict__ Kin,
    const float* __restrict__ V,
    float* __restrict__ O)
{
    extern __shared__ float sma[];
    float* Ks = sma;                  // [j][d] 64xATP
    float* Vt = sma + 64 * ATP;       // [d][j] 64xATP
    float* Ps = sma + 2 * 64 * ATP;   // Q stage, then per-warp P slabs

    const int tid  = threadIdx.x;
    const int wid  = tid >> 5, lane = tid & 31;
    const int g    = lane >> 2, t = lane & 3;
    const int b    = blockIdx.z;
    const int h    = blockIdx.y;
    const int q0   = blockIdx.x * 64;
    const float C2 = 0.125f * 1.44269504088896340736f;   // scale*log2(e)

    const float* Qg = Q   + ((size_t)b * SEQ + q0) * HID + h * HD;
    const float* Kg = Kin + (size_t)b * SEQ * HID + h * HD;
    const float* Vg = V   + (size_t)b * SEQ * HID + h * HD;

    // ---- stage Q (tf32) -> fragments ----
    for (int idx = tid; idx < 64 * 16; idx += 128) {
        const int r = idx >> 4, d4 = (idx & 15) * 4;
        float4 v = *(const float4*)(Qg + (size_t)r * HID + d4);
        float* d = Ps + r * ATP + d4;
        d[0] = tf32r(v.x); d[1] = tf32r(v.y); d[2] = tf32r(v.z); d[3] = tf32r(v.w);
    }
    __syncthreads();

    uint32_t qf[8][4];
    #pragma unroll
    for (int ks = 0; ks < 8; ks++) {
        const float* qp = Ps + wid * 16 * ATP + ks * 8;
        qf[ks][0] = __float_as_uint(qp[ g      * ATP + t    ]);
        qf[ks][1] = __float_as_uint(qp[(g + 8) * ATP + t    ]);
        qf[ks][2] = __float_as_uint(qp[ g      * ATP + t + 4]);
        qf[ks][3] = __float_as_uint(qp[(g + 8) * ATP + t + 4]);
    }
    __syncthreads();

    float oacc[8][4] = {};
    float m0 = -1e30f, m1 = -1e30f, l0 = 0.0f, l1 = 0.0f;

    // staging maps (128 threads)
    const int jk = tid >> 1, dk = (tid & 1) * 32;    // K: [j][d]
    const int jv = tid & 63, dv = (tid >> 6) * 32;   // V: write [d][j]

    float* Pw = Ps + wid * 16 * ATP;

    for (int kv0 = 0; kv0 < SEQ; kv0 += 64) {
        __syncthreads();   // prior tile's consumers done
        #pragma unroll
        for (int i = 0; i < 8; i++) {
            float4 kv4 = *(const float4*)(Kg + (size_t)(kv0 + jk) * HID + dk + 4 * i);
            float* kd = Ks + jk * ATP + dk + 4 * i;
            kd[0] = tf32r(kv4.x); kd[1] = tf32r(kv4.y);
            kd[2] = tf32r(kv4.z); kd[3] = tf32r(kv4.w);
        }
        #pragma unroll
        for (int i = 0; i < 8; i++) {
            float4 vv = *(const float4*)(Vg + (size_t)(kv0 + jv) * HID + dv + 4 * i);
            const int d = dv + 4 * i;
            Vt[(d + 0) * ATP + jv] = tf32r(vv.x);
            Vt[(d + 1) * ATP + jv] = tf32r(vv.y);
            Vt[(d + 2) * ATP + jv] = tf32r(vv.z);
            Vt[(d + 3) * ATP + jv] = tf32r(vv.w);
        }
        __syncthreads();

        // ---- S = Q K^T ----
        float s[8][4] = {};
        #pragma unroll
        for (int ks = 0; ks < 8; ks++) {
            #pragma unroll
            for (int nt = 0; nt < 8; nt++) {
                const float* bp = Ks + (nt * 8 + g) * ATP + ks * 8 + t;
                uint32_t b0 = __float_as_uint(bp[0]);
                uint32_t b1 = __float_as_uint(bp[4]);
                mma_tf32(s[nt], qf[ks], b0, b1);
            }
        }

        // ---- online softmax (raw-score max, exp2-folded) ----
        float rm0 = -1e30f, rm1 = -1e30f;
        #pragma unroll
        for (int nt = 0; nt < 8; nt++) {
            rm0 = fmaxf(rm0, fmaxf(s[nt][0], s[nt][1]));
            rm1 = fmaxf(rm1, fmaxf(s[nt][2], s[nt][3]));
        }
        rm0 = fmaxf(rm0, __shfl_xor_sync(0xffffffffu, rm0, 1));
        rm0 = fmaxf(rm0, __shfl_xor_sync(0xffffffffu, rm0, 2));
        rm1 = fmaxf(rm1, __shfl_xor_sync(0xffffffffu, rm1, 1));
        rm1 = fmaxf(rm1, __shfl_xor_sync(0xffffffffu, rm1, 2));

        const float nm0 = fmaxf(m0, rm0), nm1 = fmaxf(m1, rm1);
        const float a0 = exp2f((m0 - nm0) * C2), a1 = exp2f((m1 - nm1) * C2);
        const float mc0 = nm0 * C2, mc1 = nm1 * C2;
        float sum0 = 0.0f, sum1 = 0.0f;
        #pragma unroll
        for (int nt = 0; nt < 8; nt++) {
            s[nt][0] = exp2f(fmaf(s[nt][0], C2, -mc0)); sum0 += s[nt][0];
            s[nt][1] = exp2f(fmaf(s[nt][1], C2, -mc0)); sum0 += s[nt][1];
            s[nt][2] = exp2f(fmaf(s[nt][2], C2, -mc1)); sum1 += s[nt][2];
            s[nt][3] = exp2f(fmaf(s[nt][3], C2, -mc1)); sum1 += s[nt][3];
        }
        sum0 += __shfl_xor_sync(0xffffffffu, sum0, 1);
        sum0 += __shfl_xor_sync(0xffffffffu, sum0, 2);
        sum1 += __shfl_xor_sync(0xffffffffu, sum1, 1);
        sum1 += __shfl_xor_sync(0xffffffffu, sum1, 2);

        l0 = l0 * a0 + sum0; l1 = l1 * a1 + sum1;
        m0 = nm0; m1 = nm1;
        #pragma unroll
        for (int nt = 0; nt < 8; nt++) {
            oacc[nt][0] *= a0; oacc[nt][1] *= a0;
            oacc[nt][2] *= a1; oacc[nt][3] *= a1;
        }

        // ---- stage P (warp-private, float2) ----
        #pragma unroll
        for (int nt = 0; nt < 8; nt++) {
            float2 p0 = {tf32r(s[nt][0]), tf32r(s[nt][1])};
            float2 p1 = {tf32r(s[nt][2]), tf32r(s[nt][3])};
            *(float2*)&Pw[ g      * ATP + nt * 8 + 2 * t] = p0;
            *(float2*)&Pw[(g + 8) * ATP + nt * 8 + 2 * t] = p1;
        }
        __syncwarp();

        // ---- O += P V ----
        #pragma unroll
        for (int ks = 0; ks < 8; ks++) {
            uint32_t af[4];
            af[0] = __float_as_uint(Pw[ g      * ATP + ks * 8 + t    ]);
            af[1] = __float_as_uint(Pw[(g + 8) * ATP + ks * 8 + t    ]);
            af[2] = __float_as_uint(Pw[ g      * ATP + ks * 8 + t + 4]);
            af[3] = __float_as_uint(Pw[(g + 8) * ATP + ks * 8 + t + 4]);
            #pragma unroll
            for (int nt = 0; nt < 8; nt++) {
                const float* bp = Vt + (nt * 8 + g) * ATP + ks * 8 + t;
                uint32_t b0 = __float_as_uint(bp[0]);
                uint32_t b1 = __float_as_uint(bp[4]);
                mma_tf32(oacc[nt], af, b0, b1);
            }
        }
    }

    // ---- epilogue ----
    const float inv0 = 1.0f / l0, inv1 = 1.0f / l1;
    float* Og = O + ((size_t)b * SEQ + q0 + wid * 16) * HID + h * HD;
    #pragma unroll
    for (int nt = 0; nt < 8; nt++) {
        const int col = nt * 8 + 2 * t;
        float2 v0 = {oacc[nt][0] * inv0, oacc[nt][1] * inv0};
        float2 v1 = {oacc[nt][2] * inv1, oacc[nt][3] * inv1};
        *(float2*)&Og[(size_t) g      * HID + col] = v0;
        *(float2*)&Og[(size_t)(g + 8) * HID + col] = v1;
    }
}

// ===========================================================================
extern "C" void kernel_launch(void* const* d_in, const int* in_sizes, int n_in,
                              void* d_out, int out_size)
{
    const float* q   = (const float*)d_in[0];
    const float* Wq  = (const float*)d_in[1];
    const float* bq  = (const float*)d_in[2];
    const float* Wkv = (const float*)d_in[3];
    const float* bkv = (const float*)d_in[4];
    const float* Wo  = (const float*)d_in[5];
    const float* bo  = (const float*)d_in[6];
    float* out = (float*)d_out;

    void *pQ, *pK, *pV, *pO;
    cudaGetSymbolAddress(&pQ, g_Q);
    cudaGetSymbolAddress(&pK, g_K);
    cudaGetSymbolAddress(&pV, g_V);
    cudaGetSymbolAddress(&pO, g_O);
    float* gQ = (float*)pQ;
    float* gK = (float*)pK;
    float* gV = (float*)pV;
    float* gO = (float*)pO;

    cudaFuncSetAttribute(gemm_tc, cudaFuncAttributeMaxDynamicSharedMemorySize,
                         GEMM_SMEM);
    cudaFuncSetAttribute(attn_tc, cudaFuncAttributeMaxDynamicSharedMemorySize,
                         ATTN_SMEM);

    dim3 ggrid(HID / 128, MROWS / 128);

    gemm_tc<<<ggrid, 256, GEMM_SMEM>>>(q, HID, Wq, HID, bq, gQ, HID, HID);
    gemm_tc<<<ggrid, 256, GEMM_SMEM>>>(q, HID, Wkv, 2 * HID, bkv, gK, HID, HID);
    gemm_tc<<<ggrid, 256, GEMM_SMEM>>>(q, HID, Wkv + HID, 2 * HID, bkv + HID,
                                       gV, HID, HID);

    dim3 agrid(SEQ / 64, NH, BATCH);     // (32, 16, 2) = 1024 CTAs
    attn_tc<<<agrid, 128, ATTN_SMEM>>>(gQ, gK, gV, gO);

    gemm_tc<<<ggrid, 256, GEMM_SMEM>>>(gO, HID, Wo, HID, bo, out, HID, HID);
}

// round 7
// speedup vs baseline: 1.3192x; 1.3123x over previous
#include <cuda_runtime.h>
#include <cstdint>

// ---------------------------------------------------------------------------
// MHA on mma.sync m16n8k8 tf32.  R7 (= R6 resubmit after infra failure):
// attention smem-traffic halving — warp M-tile doubled to 32 q rows (each
// B fragment feeds 2 mmas), 256 q rows/CTA, 8 warps. GEMMs unchanged.
// ---------------------------------------------------------------------------

#define SEQ     2048
#define BATCH   2
#define NH      16
#define HD      64
#define HID     1024
#define MROWS   (BATCH * SEQ)   // 4096

__device__ float g_Q[MROWS * HID];
__device__ float g_K[MROWS * HID];
__device__ float g_V[MROWS * HID];
__device__ float g_O[MROWS * HID];

// ------------------------------ helpers ------------------------------------
__device__ __forceinline__ float tf32r(float f) {
    uint32_t r;
    asm("cvt.rna.tf32.f32 %0, %1;" : "=r"(r) : "f"(f));
    return __uint_as_float(r);
}

__device__ __forceinline__ void mma_tf32(float* d, const uint32_t* a,
                                         uint32_t b0, uint32_t b1) {
    asm volatile(
        "mma.sync.aligned.m16n8k8.row.col.f32.tf32.tf32.f32 "
        "{%0,%1,%2,%3}, {%4,%5,%6,%7}, {%8,%9}, {%0,%1,%2,%3};"
        : "+f"(d[0]), "+f"(d[1]), "+f"(d[2]), "+f"(d[3])
        : "r"(a[0]), "r"(a[1]), "r"(a[2]), "r"(a[3]), "r"(b0), "r"(b1));
}

// ============================ tf32 GEMM (unchanged, passing) ================
#define PADA 36
#define PADB 136
#define GEMM_SMEM ((2 * (128 * PADA + 32 * PADB)) * (int)sizeof(float))

__global__ __launch_bounds__(256) void gemm_tc(
    const float* __restrict__ A, int lda,
    const float* __restrict__ B, int ldb,
    const float* __restrict__ bias,
    float* __restrict__ C, int ldc, int K)
{
    extern __shared__ float smg[];
    float* As = smg;
    float* Bs = smg + 2 * 128 * PADA;

    const int tid  = threadIdx.x;
    const int wid  = tid >> 5, lane = tid & 31;
    const int g    = lane >> 2, t = lane & 3;
    const int wr   = wid & 1,  wc = wid >> 1;
    const int row0 = blockIdx.y * 128;
    const int col0 = blockIdx.x * 128;

    const int ar = tid >> 3, ac = (tid & 7) * 4;
    const int br = tid >> 3, bc = (tid & 7) * 4;

    const float* Ag = A + (size_t)row0 * lda;
    const float* Bg = B + col0;

    float4 ra[4], rb[4];
    const int NT = K >> 5;

    #pragma unroll
    for (int i = 0; i < 4; i++)
        ra[i] = *(const float4*)(Ag + (size_t)(ar + 32 * i) * lda + ac);
    #pragma unroll
    for (int j = 0; j < 4; j++)
        rb[j] = *(const float4*)(Bg + (size_t)br * ldb + bc + 32 * j);
    {
        #pragma unroll
        for (int i = 0; i < 4; i++) {
            float* d = As + (ar + 32 * i) * PADA + ac;
            d[0] = tf32r(ra[i].x); d[1] = tf32r(ra[i].y);
            d[2] = tf32r(ra[i].z); d[3] = tf32r(ra[i].w);
        }
        #pragma unroll
        for (int j = 0; j < 4; j++) {
            float* d = Bs + br * PADB + bc + 32 * j;
            d[0] = tf32r(rb[j].x); d[1] = tf32r(rb[j].y);
            d[2] = tf32r(rb[j].z); d[3] = tf32r(rb[j].w);
        }
    }
    __syncthreads();

    float acc[4][4][4] = {};

    for (int kt = 0; kt < NT; kt++) {
        if (kt + 1 < NT) {
            const int k0 = (kt + 1) * 32;
            #pragma unroll
            for (int i = 0; i < 4; i++)
                ra[i] = *(const float4*)(Ag + (size_t)(ar + 32 * i) * lda + k0 + ac);
            #pragma unroll
            for (int j = 0; j < 4; j++)
                rb[j] = *(const float4*)(Bg + (size_t)(k0 + br) * ldb + bc + 32 * j);
        }

        const float* Ac = As + (kt & 1) * 128 * PADA;
        const float* Bc = Bs + (kt & 1) * 32 * PADB;

        #pragma unroll
        for (int kk = 0; kk < 4; kk++) {
            uint32_t af[4][4];
            #pragma unroll
            for (int mt = 0; mt < 4; mt++) {
                const float* ap = Ac + (wr * 64 + mt * 16) * PADA + kk * 8;
                af[mt][0] = __float_as_uint(ap[ g      * PADA + t    ]);
                af[mt][1] = __float_as_uint(ap[(g + 8) * PADA + t    ]);
                af[mt][2] = __float_as_uint(ap[ g      * PADA + t + 4]);
                af[mt][3] = __float_as_uint(ap[(g + 8) * PADA + t + 4]);
            }
            #pragma unroll
            for (int nt = 0; nt < 4; nt++) {
                const float* bp = Bc + kk * 8 * PADB + wc * 32 + nt * 8 + g;
                uint32_t b0 = __float_as_uint(bp[ t      * PADB]);
                uint32_t b1 = __float_as_uint(bp[(t + 4) * PADB]);
                #pragma unroll
                for (int mt = 0; mt < 4; mt++)
                    mma_tf32(acc[mt][nt], af[mt], b0, b1);
            }
        }

        if (kt + 1 < NT) {
            __syncthreads();
            float* Ad = As + ((kt + 1) & 1) * 128 * PADA;
            float* Bd = Bs + ((kt + 1) & 1) * 32 * PADB;
            #pragma unroll
            for (int i = 0; i < 4; i++) {
                float* d = Ad + (ar + 32 * i) * PADA + ac;
                d[0] = tf32r(ra[i].x); d[1] = tf32r(ra[i].y);
                d[2] = tf32r(ra[i].z); d[3] = tf32r(ra[i].w);
            }
            #pragma unroll
            for (int j = 0; j < 4; j++) {
                float* d = Bd + br * PADB + bc + 32 * j;
                d[0] = tf32r(rb[j].x); d[1] = tf32r(rb[j].y);
                d[2] = tf32r(rb[j].z); d[3] = tf32r(rb[j].w);
            }
            __syncthreads();
        }
    }

    #pragma unroll
    for (int mt = 0; mt < 4; mt++) {
        const int row = row0 + wr * 64 + mt * 16 + g;
        #pragma unroll
        for (int nt = 0; nt < 4; nt++) {
            const int col = col0 + wc * 32 + nt * 8 + 2 * t;
            float2 bb = *(const float2*)&bias[col];
            float2 v0 = {acc[mt][nt][0] + bb.x, acc[mt][nt][1] + bb.y};
            float2 v1 = {acc[mt][nt][2] + bb.x, acc[mt][nt][3] + bb.y};
            *(float2*)&C[(size_t)row * ldc + col]       = v0;
            *(float2*)&C[(size_t)(row + 8) * ldc + col] = v1;
        }
    }
}

// ============================ attention ====================================
// 256 q rows/CTA, 8 warps x 32 q rows (mt=2).  Each B fragment (2 LDS)
// feeds 2 mmas -> B smem traffic per mma halved vs R3.
#define ATP 68
#define ATTN_SMEM ((2 * 64 * ATP + 256 * ATP) * (int)sizeof(float))   // 104448

__global__ __launch_bounds__(256, 1) void attn_tc(
    const float* __restrict__ Q,
    const float* __restrict__ Kin,
    const float* __restrict__ V,
    float* __restrict__ O)
{
    extern __shared__ float sma[];
    float* Ks = sma;                   // [j][d] 64xATP
    float* Vt = sma + 64 * ATP;        // [d][j] 64xATP
    float* Ps = sma + 2 * 64 * ATP;    // Q stage (256xATP), then P slabs (8w x 32r)

    const int tid  = threadIdx.x;
    const int wid  = tid >> 5, lane = tid & 31;
    const int g    = lane >> 2, t = lane & 3;
    const int b    = blockIdx.z;
    const int h    = blockIdx.y;
    const int q0   = blockIdx.x * 256;
    const float C2 = 0.125f * 1.44269504088896340736f;   // scale*log2(e)

    const float* Qg = Q   + ((size_t)b * SEQ + q0) * HID + h * HD;
    const float* Kg = Kin + (size_t)b * SEQ * HID + h * HD;
    const float* Vg = V   + (size_t)b * SEQ * HID + h * HD;

    // ---- stage Q (tf32) into Ps, preload fragments, then Ps is P slabs ----
    for (int idx = tid; idx < 256 * 16; idx += 256) {
        const int r = idx >> 4, d4 = (idx & 15) * 4;
        float4 v = *(const float4*)(Qg + (size_t)r * HID + d4);
        float* d = Ps + r * ATP + d4;
        d[0] = tf32r(v.x); d[1] = tf32r(v.y); d[2] = tf32r(v.z); d[3] = tf32r(v.w);
    }
    __syncthreads();

    uint32_t qf[2][8][4];
    #pragma unroll
    for (int mt = 0; mt < 2; mt++) {
        #pragma unroll
        for (int ks = 0; ks < 8; ks++) {
            const float* qp = Ps + (wid * 32 + mt * 16) * ATP + ks * 8;
            qf[mt][ks][0] = __float_as_uint(qp[ g      * ATP + t    ]);
            qf[mt][ks][1] = __float_as_uint(qp[(g + 8) * ATP + t    ]);
            qf[mt][ks][2] = __float_as_uint(qp[ g      * ATP + t + 4]);
            qf[mt][ks][3] = __float_as_uint(qp[(g + 8) * ATP + t + 4]);
        }
    }
    __syncthreads();

    float oacc[2][8][4] = {};
    float m[2][2], l[2][2];
    #pragma unroll
    for (int mt = 0; mt < 2; mt++) {
        m[mt][0] = -1e30f; m[mt][1] = -1e30f;
        l[mt][0] = 0.0f;   l[mt][1] = 0.0f;
    }

    // staging maps (256 threads)
    const int jk = tid >> 2, dk = (tid & 3) * 16;    // K: [j][d]
    const int jv = tid & 63, dv = (tid >> 6) * 16;   // V: write [d][j]

    float* Pw = Ps + wid * 32 * ATP;

    for (int kv0 = 0; kv0 < SEQ; kv0 += 64) {
        __syncthreads();   // prior tile's consumers (incl. PV reads) done
        #pragma unroll
        for (int i = 0; i < 4; i++) {
            float4 kv4 = *(const float4*)(Kg + (size_t)(kv0 + jk) * HID + dk + 4 * i);
            float* kd = Ks + jk * ATP + dk + 4 * i;
            kd[0] = tf32r(kv4.x); kd[1] = tf32r(kv4.y);
            kd[2] = tf32r(kv4.z); kd[3] = tf32r(kv4.w);
        }
        #pragma unroll
        for (int i = 0; i < 4; i++) {
            float4 vv = *(const float4*)(Vg + (size_t)(kv0 + jv) * HID + dv + 4 * i);
            const int d = dv + 4 * i;
            Vt[(d + 0) * ATP + jv] = tf32r(vv.x);
            Vt[(d + 1) * ATP + jv] = tf32r(vv.y);
            Vt[(d + 2) * ATP + jv] = tf32r(vv.z);
            Vt[(d + 3) * ATP + jv] = tf32r(vv.w);
        }
        __syncthreads();

        // ---- S = Q K^T : one B load feeds both mt ----
        float s[2][8][4] = {};
        #pragma unroll
        for (int nt = 0; nt < 8; nt++) {
            #pragma unroll
            for (int ks = 0; ks < 8; ks++) {
                const float* bp = Ks + (nt * 8 + g) * ATP + ks * 8 + t;
                uint32_t b0 = __float_as_uint(bp[0]);
                uint32_t b1 = __float_as_uint(bp[4]);
                mma_tf32(s[0][nt], qf[0][ks], b0, b1);
                mma_tf32(s[1][nt], qf[1][ks], b0, b1);
            }
        }

        // ---- online softmax per mt (raw-score max, exp2-folded) ----
        #pragma unroll
        for (int mt = 0; mt < 2; mt++) {
            float rm0 = -1e30f, rm1 = -1e30f;
            #pragma unroll
            for (int nt = 0; nt < 8; nt++) {
                rm0 = fmaxf(rm0, fmaxf(s[mt][nt][0], s[mt][nt][1]));
                rm1 = fmaxf(rm1, fmaxf(s[mt][nt][2], s[mt][nt][3]));
            }
            rm0 = fmaxf(rm0, __shfl_xor_sync(0xffffffffu, rm0, 1));
            rm0 = fmaxf(rm0, __shfl_xor_sync(0xffffffffu, rm0, 2));
            rm1 = fmaxf(rm1, __shfl_xor_sync(0xffffffffu, rm1, 1));
            rm1 = fmaxf(rm1, __shfl_xor_sync(0xffffffffu, rm1, 2));

            const float nm0 = fmaxf(m[mt][0], rm0), nm1 = fmaxf(m[mt][1], rm1);
            const float a0 = exp2f((m[mt][0] - nm0) * C2);
            const float a1 = exp2f((m[mt][1] - nm1) * C2);
            const float mc0 = nm0 * C2, mc1 = nm1 * C2;
            float sum0 = 0.0f, sum1 = 0.0f;
            #pragma unroll
            for (int nt = 0; nt < 8; nt++) {
                s[mt][nt][0] = exp2f(fmaf(s[mt][nt][0], C2, -mc0)); sum0 += s[mt][nt][0];
                s[mt][nt][1] = exp2f(fmaf(s[mt][nt][1], C2, -mc0)); sum0 += s[mt][nt][1];
                s[mt][nt][2] = exp2f(fmaf(s[mt][nt][2], C2, -mc1)); sum1 += s[mt][nt][2];
                s[mt][nt][3] = exp2f(fmaf(s[mt][nt][3], C2, -mc1)); sum1 += s[mt][nt][3];
            }
            sum0 += __shfl_xor_sync(0xffffffffu, sum0, 1);
            sum0 += __shfl_xor_sync(0xffffffffu, sum0, 2);
            sum1 += __shfl_xor_sync(0xffffffffu, sum1, 1);
            sum1 += __shfl_xor_sync(0xffffffffu, sum1, 2);

            l[mt][0] = l[mt][0] * a0 + sum0;
            l[mt][1] = l[mt][1] * a1 + sum1;
            m[mt][0] = nm0; m[mt][1] = nm1;
            #pragma unroll
            for (int nt = 0; nt < 8; nt++) {
                oacc[mt][nt][0] *= a0; oacc[mt][nt][1] *= a0;
                oacc[mt][nt][2] *= a1; oacc[mt][nt][3] *= a1;
            }

            // stage P (warp-private, float2)
            #pragma unroll
            for (int nt = 0; nt < 8; nt++) {
                float2 p0 = {tf32r(s[mt][nt][0]), tf32r(s[mt][nt][1])};
                float2 p1 = {tf32r(s[mt][nt][2]), tf32r(s[mt][nt][3])};
                *(float2*)&Pw[(mt * 16 + g    ) * ATP + nt * 8 + 2 * t] = p0;
                *(float2*)&Pw[(mt * 16 + g + 8) * ATP + nt * 8 + 2 * t] = p1;
            }
        }
        __syncwarp();

        // ---- O += P V : one B load feeds both mt ----
        #pragma unroll
        for (int ks = 0; ks < 8; ks++) {
            uint32_t af[2][4];
            #pragma unroll
            for (int mt = 0; mt < 2; mt++) {
                const float* pp = Pw + mt * 16 * ATP + ks * 8;
                af[mt][0] = __float_as_uint(pp[ g      * ATP + t    ]);
                af[mt][1] = __float_as_uint(pp[(g + 8) * ATP + t    ]);
                af[mt][2] = __float_as_uint(pp[ g      * ATP + t + 4]);
                af[mt][3] = __float_as_uint(pp[(g + 8) * ATP + t + 4]);
            }
            #pragma unroll
            for (int nt = 0; nt < 8; nt++) {
                const float* bp = Vt + (nt * 8 + g) * ATP + ks * 8 + t;
                uint32_t b0 = __float_as_uint(bp[0]);
                uint32_t b1 = __float_as_uint(bp[4]);
                mma_tf32(oacc[0][nt], af[0], b0, b1);
                mma_tf32(oacc[1][nt], af[1], b0, b1);
            }
        }
        __syncwarp();
    }

    // ---- epilogue ----
    #pragma unroll
    for (int mt = 0; mt < 2; mt++) {
        const float inv0 = 1.0f / l[mt][0], inv1 = 1.0f / l[mt][1];
        float* Og = O + ((size_t)b * SEQ + q0 + wid * 32 + mt * 16) * HID + h * HD;
        #pragma unroll
        for (int nt = 0; nt < 8; nt++) {
            const int col = nt * 8 + 2 * t;
            float2 v0 = {oacc[mt][nt][0] * inv0, oacc[mt][nt][1] * inv0};
            float2 v1 = {oacc[mt][nt][2] * inv1, oacc[mt][nt][3] * inv1};
            *(float2*)&Og[(size_t) g      * HID + col] = v0;
            *(float2*)&Og[(size_t)(g + 8) * HID + col] = v1;
        }
    }
}

// ===========================================================================
extern "C" void kernel_launch(void* const* d_in, const int* in_sizes, int n_in,
                              void* d_out, int out_size)
{
    const float* q   = (const float*)d_in[0];
    const float* Wq  = (const float*)d_in[1];
    const float* bq  = (const float*)d_in[2];
    const float* Wkv = (const float*)d_in[3];
    const float* bkv = (const float*)d_in[4];
    const float* Wo  = (const float*)d_in[5];
    const float* bo  = (const float*)d_in[6];
    float* out = (float*)d_out;

    void *pQ, *pK, *pV, *pO;
    cudaGetSymbolAddress(&pQ, g_Q);
    cudaGetSymbolAddress(&pK, g_K);
    cudaGetSymbolAddress(&pV, g_V);
    cudaGetSymbolAddress(&pO, g_O);
    float* gQ = (float*)pQ;
    float* gK = (float*)pK;
    float* gV = (float*)pV;
    float* gO = (float*)pO;

    cudaFuncSetAttribute(gemm_tc, cudaFuncAttributeMaxDynamicSharedMemorySize,
                         GEMM_SMEM);
    cudaFuncSetAttribute(attn_tc, cudaFuncAttributeMaxDynamicSharedMemorySize,
                         ATTN_SMEM);

    dim3 ggrid(HID / 128, MROWS / 128);

    gemm_tc<<<ggrid, 256, GEMM_SMEM>>>(q, HID, Wq, HID, bq, gQ, HID, HID);
    gemm_tc<<<ggrid, 256, GEMM_SMEM>>>(q, HID, Wkv, 2 * HID, bkv, gK, HID, HID);
    gemm_tc<<<ggrid, 256, GEMM_SMEM>>>(q, HID, Wkv + HID, 2 * HID, bkv + HID,
                                       gV, HID, HID);

    dim3 agrid(SEQ / 256, NH, BATCH);     // (8, 16, 2) = 256 CTAs
    attn_tc<<<agrid, 256, ATTN_SMEM>>>(gQ, gK, gV, gO);

    gemm_tc<<<ggrid, 256, GEMM_SMEM>>>(gO, HID, Wo, HID, bo, out, HID, HID);
}